// round 1
// baseline (speedup 1.0000x reference)
#include <cuda_runtime.h>
#include <math.h>

#define NODES 100000
#define EDGES 1600000

// ---------------- scratch (device globals: allocation-free) ----------------
__device__ int   g_deg[NODES];
__device__ int   g_fill[NODES];
__device__ int   g_ptr[NODES + 1];
__device__ int   g_bsum[128];
__device__ int   g_csr[EDGES];
__device__ float g_inv[NODES];
__device__ float g_h0[NODES * 64];
__device__ float g_h1[NODES * 64];
__device__ float g_agg[NODES * 64];

// ---------------- CSR build ----------------
__global__ void k_zero() {
    int i = blockIdx.x * blockDim.x + threadIdx.x;
    if (i < NODES) { g_deg[i] = 0; g_fill[i] = 0; }
}

__global__ void k_hist(const int* __restrict__ dst) {
    int e = blockIdx.x * blockDim.x + threadIdx.x;
    if (e < EDGES) atomicAdd(&g_deg[dst[e]], 1);
}

// block-wise exclusive scan (1024/block) + block totals
__global__ void k_scan1() {
    __shared__ int sh[1024];
    int tid = threadIdx.x;
    int i = blockIdx.x * 1024 + tid;
    int v = (i < NODES) ? g_deg[i] : 0;
    sh[tid] = v;
    __syncthreads();
    for (int off = 1; off < 1024; off <<= 1) {
        int t = (tid >= off) ? sh[tid - off] : 0;
        __syncthreads();
        sh[tid] += t;
        __syncthreads();
    }
    if (i < NODES) g_ptr[i] = sh[tid] - v;        // exclusive, pre-offset
    if (tid == 1023) g_bsum[blockIdx.x] = sh[1023];
}

__global__ void k_scan2(int nb) {
    __shared__ int sh[128];
    int tid = threadIdx.x;
    int v = (tid < nb) ? g_bsum[tid] : 0;
    sh[tid] = v;
    __syncthreads();
    for (int off = 1; off < 128; off <<= 1) {
        int t = (tid >= off) ? sh[tid - off] : 0;
        __syncthreads();
        sh[tid] += t;
        __syncthreads();
    }
    if (tid < nb) g_bsum[tid] = sh[tid] - v;      // exclusive block offsets
}

__global__ void k_scan3() {
    int tid = threadIdx.x;
    int i = blockIdx.x * 1024 + tid;
    if (i < NODES) {
        g_ptr[i] += g_bsum[blockIdx.x];
        int d = g_deg[i];
        g_inv[i] = (d > 0) ? (1.0f / (float)d) : 0.0f;
    }
    if (i == 0) g_ptr[NODES] = EDGES;
}

__global__ void k_fill(const int* __restrict__ src, const int* __restrict__ dst) {
    int e = blockIdx.x * blockDim.x + threadIdx.x;
    if (e < EDGES) {
        int d = dst[e];
        int pos = g_ptr[d] + atomicAdd(&g_fill[d], 1);
        g_csr[pos] = src[e];
    }
}

// ---------------- mean aggregation (warp per node, CSR pull, no atomics) ----------------
template <int D>
__global__ void __launch_bounds__(256) k_aggregate(const float* __restrict__ hin,
                                                   float* __restrict__ aggout) {
    int node = blockIdx.x * 8 + (threadIdx.x >> 5);
    if (node >= NODES) return;
    int lane = threadIdx.x & 31;
    int beg = g_ptr[node], end = g_ptr[node + 1];
    float iv = g_inv[node];

    if (D == 64) {
        const float2* __restrict__ h2 = (const float2*)hin;  // 32 float2 per row
        float sx = 0.f, sy = 0.f;
        int k = beg;
        for (; k + 3 < end; k += 4) {
            int s0 = g_csr[k], s1 = g_csr[k + 1], s2 = g_csr[k + 2], s3 = g_csr[k + 3];
            float2 a = h2[s0 * 32 + lane];
            float2 b = h2[s1 * 32 + lane];
            float2 c = h2[s2 * 32 + lane];
            float2 d = h2[s3 * 32 + lane];
            sx += (a.x + b.x) + (c.x + d.x);
            sy += (a.y + b.y) + (c.y + d.y);
        }
        for (; k < end; k++) {
            float2 a = h2[g_csr[k] * 32 + lane];
            sx += a.x; sy += a.y;
        }
        ((float2*)aggout)[node * 32 + lane] = make_float2(sx * iv, sy * iv);
    } else {  // D == 32
        float s = 0.f;
        int k = beg;
        for (; k + 3 < end; k += 4) {
            int s0 = g_csr[k], s1 = g_csr[k + 1], s2 = g_csr[k + 2], s3 = g_csr[k + 3];
            s += hin[s0 * 32 + lane] + hin[s1 * 32 + lane]
               + hin[s2 * 32 + lane] + hin[s3 * 32 + lane];
        }
        for (; k < end; k++) s += hin[g_csr[k] * 32 + lane];
        aggout[node * 32 + lane] = s * iv;
    }
}

// ---------------- fused SAGE transform: out = [relu](agg@Wn + bn + h@Wr) ----------------
// 32 nodes per block (4 warps x 8 nodes). Lane owns output features (2l, 2l+1).
template <int DIN, bool RELU>
__global__ void __launch_bounds__(128) k_layer(const float* __restrict__ agg,
                                               const float* __restrict__ hin,
                                               const float* __restrict__ Wn,
                                               const float* __restrict__ bn,
                                               const float* __restrict__ Wr,
                                               float* __restrict__ hout) {
    __shared__ float2 sWn[DIN * 32];   // Wn[i][2l..2l+1]
    __shared__ float2 sWr[DIN * 32];
    __shared__ float2 sAH[32 * DIN];   // (agg, h) interleaved per [node][i]
    int tid = threadIdx.x;

    const float2* Wn2 = (const float2*)Wn;
    const float2* Wr2 = (const float2*)Wr;
    for (int idx = tid; idx < DIN * 32; idx += 128) {
        sWn[idx] = Wn2[idx];
        sWr[idx] = Wr2[idx];
    }
    int n0 = blockIdx.x * 32;
    const float* aggB = agg + (size_t)n0 * DIN;
    const float* hB   = hin + (size_t)n0 * DIN;
    for (int idx = tid; idx < 32 * DIN; idx += 128)
        sAH[idx] = make_float2(aggB[idx], hB[idx]);
    __syncthreads();

    int w = tid >> 5, lane = tid & 31;
    int sbase = w * 8;

    float2 b2 = ((const float2*)bn)[lane];
    float2 acc[8];
#pragma unroll
    for (int s = 0; s < 8; s++) acc[s] = b2;

#pragma unroll 4
    for (int i = 0; i < DIN; i++) {
        float2 wn = sWn[i * 32 + lane];
        float2 wr = sWr[i * 32 + lane];
#pragma unroll
        for (int s = 0; s < 8; s++) {
            float2 ah = sAH[(sbase + s) * DIN + i];   // broadcast LDS.64
            acc[s].x += ah.x * wn.x + ah.y * wr.x;
            acc[s].y += ah.x * wn.y + ah.y * wr.y;
        }
    }

#pragma unroll
    for (int s = 0; s < 8; s++) {
        float2 v = acc[s];
        if (RELU) { v.x = fmaxf(v.x, 0.f); v.y = fmaxf(v.y, 0.f); }
        *(float2*)(hout + (size_t)(n0 + sbase + s) * 64 + 2 * lane) = v;
    }
}

// ---------------- predictor head: sigmoid(relu(h@Wp1+bp1)@Wp2 + bp2) ----------------
__global__ void __launch_bounds__(128) k_pred(const float* __restrict__ h,
                                              const float* __restrict__ Wp1,
                                              const float* __restrict__ bp1,
                                              const float* __restrict__ Wp2,
                                              const float* __restrict__ bp2,
                                              float* __restrict__ out) {
    __shared__ float2 sW[64 * 32];  // 16KB
    __shared__ float  sH[32 * 64];  // 8KB
    __shared__ float  sV[64];
    int tid = threadIdx.x;

    const float2* W2 = (const float2*)Wp1;
    for (int idx = tid; idx < 64 * 32; idx += 128) sW[idx] = W2[idx];
    if (tid < 64) sV[tid] = Wp2[tid];

    int n0 = blockIdx.x * 32;
    const float4* hB = (const float4*)(h + (size_t)n0 * 64);
    for (int idx = tid; idx < 32 * 16; idx += 128) ((float4*)sH)[idx] = hB[idx];
    __syncthreads();

    int w = tid >> 5, lane = tid & 31;
    int sbase = w * 8;
    float2 b2 = ((const float2*)bp1)[lane];
    float  vb = bp2[0];

    for (int s = 0; s < 8; s++) {
        float2 acc = b2;
#pragma unroll 8
        for (int i = 0; i < 64; i++) {
            float hh = sH[(sbase + s) * 64 + i];
            float2 wv = sW[i * 32 + lane];
            acc.x += hh * wv.x;
            acc.y += hh * wv.y;
        }
        acc.x = fmaxf(acc.x, 0.f);
        acc.y = fmaxf(acc.y, 0.f);
        float z = acc.x * sV[2 * lane] + acc.y * sV[2 * lane + 1];
#pragma unroll
        for (int off = 16; off; off >>= 1) z += __shfl_xor_sync(0xffffffff, z, off);
        if (lane == 0) out[n0 + sbase + s] = 1.f / (1.f + expf(-(z + vb)));
    }
}

// ---------------- launch ----------------
extern "C" void kernel_launch(void* const* d_in, const int* in_sizes, int n_in,
                              void* d_out, int out_size) {
    const float* x   = (const float*)d_in[0];
    const int*   ei  = (const int*)d_in[1];
    const int*   src = ei;
    const int*   dst = ei + EDGES;
    const float* Wn0 = (const float*)d_in[2];
    const float* bn0 = (const float*)d_in[3];
    const float* Wr0 = (const float*)d_in[4];
    const float* Wn1 = (const float*)d_in[5];
    const float* bn1 = (const float*)d_in[6];
    const float* Wr1 = (const float*)d_in[7];
    const float* Wn2 = (const float*)d_in[8];
    const float* bn2 = (const float*)d_in[9];
    const float* Wr2 = (const float*)d_in[10];
    const float* Wp1 = (const float*)d_in[11];
    const float* bp1 = (const float*)d_in[12];
    const float* Wp2 = (const float*)d_in[13];
    const float* bp2 = (const float*)d_in[14];
    float* out = (float*)d_out;

    float *pH0, *pH1, *pAgg;
    cudaGetSymbolAddress((void**)&pH0, g_h0);
    cudaGetSymbolAddress((void**)&pH1, g_h1);
    cudaGetSymbolAddress((void**)&pAgg, g_agg);

    const int SCAN_NB = (NODES + 1023) / 1024;   // 98

    // CSR build (per launch; deterministic up to fp-sum order)
    k_zero<<<(NODES + 255) / 256, 256>>>();
    k_hist<<<(EDGES + 255) / 256, 256>>>(dst);
    k_scan1<<<SCAN_NB, 1024>>>();
    k_scan2<<<1, 128>>>(SCAN_NB);
    k_scan3<<<SCAN_NB, 1024>>>();
    k_fill<<<(EDGES + 255) / 256, 256>>>(src, dst);

    const int AG_GRID = (NODES + 7) / 8;         // 12500
    const int GM_GRID = NODES / 32;              // 3125 (100000 % 32 == 0)

    // layer 0: 32 -> 64, relu
    k_aggregate<32><<<AG_GRID, 256>>>(x, pAgg);
    k_layer<32, true><<<GM_GRID, 128>>>(pAgg, x, Wn0, bn0, Wr0, pH0);
    // layer 1: 64 -> 64, relu
    k_aggregate<64><<<AG_GRID, 256>>>(pH0, pAgg);
    k_layer<64, true><<<GM_GRID, 128>>>(pAgg, pH0, Wn1, bn1, Wr1, pH1);
    // layer 2: 64 -> 64, no relu
    k_aggregate<64><<<AG_GRID, 256>>>(pH1, pAgg);
    k_layer<64, false><<<GM_GRID, 128>>>(pAgg, pH1, Wn2, bn2, Wr2, pH0);
    // predictor head
    k_pred<<<GM_GRID, 128>>>(pH0, Wp1, bp1, Wp2, bp2, out);

    (void)in_sizes; (void)n_in; (void)out_size;
}

// round 4
// speedup vs baseline: 1.0123x; 1.0123x over previous
#include <cuda_runtime.h>
#include <math.h>

#define NODES 100000
#define EDGES 1600000

typedef unsigned long long ull;

// ---------------- scratch (device globals: allocation-free) ----------------
__device__ int   g_deg[NODES];
__device__ int   g_fill[NODES];
__device__ int   g_ptr[NODES + 1];
__device__ int   g_bsum[128];
__device__ int   g_csr[EDGES];
__device__ float g_inv[NODES];
__device__ float g_h0[NODES * 64];
__device__ float g_h1[NODES * 64];

// ---------------- packed f32x2 FMA (FFMA2 — only reachable via PTX) --------
__device__ __forceinline__ ull fma2(ull a, ull b, ull c) {
    ull d;
    asm("fma.rn.f32x2 %0, %1, %2, %3;" : "=l"(d) : "l"(a), "l"(b), "l"(c));
    return d;
}
__device__ __forceinline__ ull pack2(float x, float y) {
    float2 t = make_float2(x, y);
    return *(ull*)&t;
}
__device__ __forceinline__ float2 unpack2(ull v) { return *(float2*)&v; }

// ---------------- CSR build ----------------
__global__ void k_zero() {
    int i = blockIdx.x * blockDim.x + threadIdx.x;
    if (i < NODES) { g_deg[i] = 0; g_fill[i] = 0; }
}

__global__ void k_hist(const int* __restrict__ dst) {
    int e = blockIdx.x * blockDim.x + threadIdx.x;
    if (e < EDGES) atomicAdd(&g_deg[dst[e]], 1);
}

__global__ void k_scan1() {
    __shared__ int sh[1024];
    int tid = threadIdx.x;
    int i = blockIdx.x * 1024 + tid;
    int v = (i < NODES) ? g_deg[i] : 0;
    sh[tid] = v;
    __syncthreads();
    for (int off = 1; off < 1024; off <<= 1) {
        int t = (tid >= off) ? sh[tid - off] : 0;
        __syncthreads();
        sh[tid] += t;
        __syncthreads();
    }
    if (i < NODES) g_ptr[i] = sh[tid] - v;
    if (tid == 1023) g_bsum[blockIdx.x] = sh[1023];
}

__global__ void k_scan2(int nb) {
    __shared__ int sh[128];
    int tid = threadIdx.x;
    int v = (tid < nb) ? g_bsum[tid] : 0;
    sh[tid] = v;
    __syncthreads();
    for (int off = 1; off < 128; off <<= 1) {
        int t = (tid >= off) ? sh[tid - off] : 0;
        __syncthreads();
        sh[tid] += t;
        __syncthreads();
    }
    if (tid < nb) g_bsum[tid] = sh[tid] - v;
}

__global__ void k_scan3() {
    int tid = threadIdx.x;
    int i = blockIdx.x * 1024 + tid;
    if (i < NODES) {
        g_ptr[i] += g_bsum[blockIdx.x];
        int d = g_deg[i];
        g_inv[i] = (d > 0) ? (1.0f / (float)d) : 0.0f;
    }
    if (i == 0) g_ptr[NODES] = EDGES;
}

__global__ void k_fill(const int* __restrict__ src, const int* __restrict__ dst) {
    int e = blockIdx.x * blockDim.x + threadIdx.x;
    if (e < EDGES) {
        int d = dst[e];
        int pos = g_ptr[d] + atomicAdd(&g_fill[d], 1);
        g_csr[pos] = src[e];
    }
}

// ================= fused SAGE layer =================
// Per block: 32 nodes, 128 threads (4 warps x 8 nodes).
// Phase W: pack weights (Wn[i][f], Wr[i][f]) into smem.
// Phase A: aggregate (CSR pull) into smem (agg, h) pairs.
// Phase B: GEMM with FFMA2, accumulator pair = (sum a*Wn, sum h*Wr).
// Optional PRED phase: predictor MLP fused after layer 2.
template <int DIN, bool RELU, bool PRED>
__global__ void __launch_bounds__(128) k_sage(const float* __restrict__ hin,
                                              const float* __restrict__ Wn,
                                              const float* __restrict__ bn,
                                              const float* __restrict__ Wr,
                                              const float* __restrict__ Wp1,
                                              const float* __restrict__ bp1,
                                              const float* __restrict__ Wp2,
                                              const float* __restrict__ bp2,
                                              float* __restrict__ hout,
                                              float* __restrict__ pred_out) {
    __shared__ ull sW[DIN * 64];    // (Wn,Wr) packed per [i][f]
    __shared__ ull sAH[32 * DIN];   // (agg,h) packed per [node][i]

    int tid = threadIdx.x;
    int w = tid >> 5, lane = tid & 31;
    int sb = w * 8;
    int n0 = blockIdx.x * 32;

    // ---- Phase W: interleave weights ----
    for (int idx = tid; idx < DIN * 64; idx += 128)
        sW[idx] = pack2(Wn[idx], Wr[idx]);

    // ---- Phase A: aggregate 8 nodes per warp ----
#pragma unroll 1
    for (int s = 0; s < 8; s++) {
        int sl = sb + s;
        int ng = n0 + sl;
        int beg = g_ptr[ng], end = g_ptr[ng + 1];
        float iv = g_inv[ng];
        if (DIN == 64) {
            const float2* __restrict__ h2 = (const float2*)hin;
            float sx = 0.f, sy = 0.f;
            int k = beg;
            for (; k + 3 < end; k += 4) {
                int s0 = g_csr[k], s1 = g_csr[k + 1], s2 = g_csr[k + 2], s3 = g_csr[k + 3];
                float2 a = h2[s0 * 32 + lane];
                float2 b = h2[s1 * 32 + lane];
                float2 c = h2[s2 * 32 + lane];
                float2 d = h2[s3 * 32 + lane];
                sx += (a.x + b.x) + (c.x + d.x);
                sy += (a.y + b.y) + (c.y + d.y);
            }
            for (; k < end; k++) {
                float2 a = h2[g_csr[k] * 32 + lane];
                sx += a.x; sy += a.y;
            }
            float2 own = h2[ng * 32 + lane];
            sAH[sl * 64 + 2 * lane]     = pack2(sx * iv, own.x);
            sAH[sl * 64 + 2 * lane + 1] = pack2(sy * iv, own.y);
        } else {  // DIN == 32
            float sm = 0.f;
            int k = beg;
            for (; k + 3 < end; k += 4) {
                int s0 = g_csr[k], s1 = g_csr[k + 1], s2 = g_csr[k + 2], s3 = g_csr[k + 3];
                sm += hin[s0 * 32 + lane] + hin[s1 * 32 + lane]
                    + hin[s2 * 32 + lane] + hin[s3 * 32 + lane];
            }
            for (; k < end; k++) sm += hin[g_csr[k] * 32 + lane];
            float own = hin[ng * 32 + lane];
            sAH[sl * 32 + lane] = pack2(sm * iv, own);
        }
    }
    __syncthreads();

    // ---- Phase B: GEMM, lane owns output features (2*lane, 2*lane+1) ----
    ull acc0[8], acc1[8];
#pragma unroll
    for (int s = 0; s < 8; s++) { acc0[s] = 0ull; acc1[s] = 0ull; }

#pragma unroll 4
    for (int i = 0; i < DIN; i++) {
        ull w0 = sW[i * 64 + 2 * lane];
        ull w1 = sW[i * 64 + 2 * lane + 1];
#pragma unroll
        for (int s = 0; s < 8; s++) {
            ull ah = sAH[(sb + s) * DIN + i];   // broadcast LDS.64
            acc0[s] = fma2(ah, w0, acc0[s]);
            acc1[s] = fma2(ah, w1, acc1[s]);
        }
    }

    float2 b2 = ((const float2*)bn)[lane];
    float rx[8], ry[8];
#pragma unroll
    for (int s = 0; s < 8; s++) {
        float2 v0 = unpack2(acc0[s]);
        float2 v1 = unpack2(acc1[s]);
        rx[s] = v0.x + v0.y + b2.x;
        ry[s] = v1.x + v1.y + b2.y;
        if (RELU) { rx[s] = fmaxf(rx[s], 0.f); ry[s] = fmaxf(ry[s], 0.f); }
    }

    if (!PRED) {
#pragma unroll
        for (int s = 0; s < 8; s++)
            *(float2*)(hout + (size_t)(n0 + sb + s) * 64 + 2 * lane) = make_float2(rx[s], ry[s]);
        return;
    }

    // ---- PRED phase: sigmoid(relu(h@Wp1+bp1)@Wp2 + bp2) ----
    __syncthreads();                    // everyone done reading sW/sAH
    float*  sH  = (float*)sAH;          // [32][64] h values (8KB of 16KB)
    float2* sWp = (float2*)sW;          // Wp1 as [i][pair] (16KB of 32KB)
    float*  sV  = (float*)(sW + 2048);  // Wp2[64]

#pragma unroll
    for (int s = 0; s < 8; s++) {
        sH[(sb + s) * 64 + 2 * lane]     = rx[s];
        sH[(sb + s) * 64 + 2 * lane + 1] = ry[s];
    }
    const float2* Wp12 = (const float2*)Wp1;
    for (int idx = tid; idx < 64 * 32; idx += 128) sWp[idx] = Wp12[idx];
    if (tid < 64) sV[tid] = Wp2[tid];
    __syncthreads();

    float2 bb = ((const float2*)bp1)[lane];
    float  vb = bp2[0];
#pragma unroll 1
    for (int s = 0; s < 8; s++) {
        float ax = bb.x, ay = bb.y;
#pragma unroll 8
        for (int i = 0; i < 64; i++) {
            float hh = sH[(sb + s) * 64 + i];
            float2 wv = sWp[i * 32 + lane];
            ax += hh * wv.x;
            ay += hh * wv.y;
        }
        ax = fmaxf(ax, 0.f);
        ay = fmaxf(ay, 0.f);
        float z = ax * sV[2 * lane] + ay * sV[2 * lane + 1];
#pragma unroll
        for (int off = 16; off; off >>= 1) z += __shfl_xor_sync(0xffffffff, z, off);
        if (lane == 0) pred_out[n0 + sb + s] = 1.f / (1.f + expf(-(z + vb)));
    }
}

// ---------------- launch ----------------
extern "C" void kernel_launch(void* const* d_in, const int* in_sizes, int n_in,
                              void* d_out, int out_size) {
    const float* x   = (const float*)d_in[0];
    const int*   ei  = (const int*)d_in[1];
    const int*   src = ei;
    const int*   dst = ei + EDGES;
    const float* Wn0 = (const float*)d_in[2];
    const float* bn0 = (const float*)d_in[3];
    const float* Wr0 = (const float*)d_in[4];
    const float* Wn1 = (const float*)d_in[5];
    const float* bn1 = (const float*)d_in[6];
    const float* Wr1 = (const float*)d_in[7];
    const float* Wn2 = (const float*)d_in[8];
    const float* bn2 = (const float*)d_in[9];
    const float* Wr2 = (const float*)d_in[10];
    const float* Wp1 = (const float*)d_in[11];
    const float* bp1 = (const float*)d_in[12];
    const float* Wp2 = (const float*)d_in[13];
    const float* bp2 = (const float*)d_in[14];
    float* out = (float*)d_out;

    float *pH0, *pH1;
    cudaGetSymbolAddress((void**)&pH0, g_h0);
    cudaGetSymbolAddress((void**)&pH1, g_h1);

    const int SCAN_NB = (NODES + 1023) / 1024;   // 98

    // CSR build
    k_zero<<<(NODES + 255) / 256, 256>>>();
    k_hist<<<(EDGES + 255) / 256, 256>>>(dst);
    k_scan1<<<SCAN_NB, 1024>>>();
    k_scan2<<<1, 128>>>(SCAN_NB);
    k_scan3<<<SCAN_NB, 1024>>>();
    k_fill<<<(EDGES + 255) / 256, 256>>>(src, dst);

    const int GRID = NODES / 32;   // 3125 (exact)

    // layer 0: 32 -> 64, relu (aggregate fused)
    k_sage<32, true,  false><<<GRID, 128>>>(x,   Wn0, bn0, Wr0,
                                            nullptr, nullptr, nullptr, nullptr, pH0, nullptr);
    // layer 1: 64 -> 64, relu
    k_sage<64, true,  false><<<GRID, 128>>>(pH0, Wn1, bn1, Wr1,
                                            nullptr, nullptr, nullptr, nullptr, pH1, nullptr);
    // layer 2: 64 -> 64, no relu, predictor fused
    k_sage<64, false, true ><<<GRID, 128>>>(pH1, Wn2, bn2, Wr2,
                                            Wp1, bp1, Wp2, bp2, nullptr, out);

    (void)in_sizes; (void)n_in; (void)out_size;
}

// round 6
// speedup vs baseline: 1.0864x; 1.0732x over previous
#include <cuda_runtime.h>
#include <cuda_fp16.h>
#include <math.h>

#define NODES 100000
#define EDGES 1600000
#define SCAN_NB 98   // ceil(100000/1024)

typedef unsigned long long ull;

// ---------------- scratch (device globals: allocation-free) ----------------
__device__ int     g_deg[NODES];
__device__ int     g_fill[NODES];
__device__ int     g_ptr[NODES + 1];
__device__ int     g_aggpub[SCAN_NB];
__device__ int     g_csr[EDGES];
__device__ float   g_inv[NODES];
__device__ float   g_h0[NODES * 64];
__device__ float   g_h1[NODES * 64];
__device__ __half2 g_hh0[NODES * 32];
__device__ __half2 g_hh1[NODES * 32];

// ---------------- packed f32x2 FMA (FFMA2 — only reachable via PTX) --------
__device__ __forceinline__ ull fma2(ull a, ull b, ull c) {
    ull d;
    asm("fma.rn.f32x2 %0, %1, %2, %3;" : "=l"(d) : "l"(a), "l"(b), "l"(c));
    return d;
}
__device__ __forceinline__ ull pack2(float x, float y) {
    float2 t = make_float2(x, y);
    return *(ull*)&t;
}
__device__ __forceinline__ float2 unpack2(ull v) { return *(float2*)&v; }

// ---------------- CSR build ----------------
__global__ void k_hist(const int* __restrict__ dst) {
    int e = blockIdx.x * blockDim.x + threadIdx.x;
    if (e < EDGES) atomicAdd(&g_deg[dst[e]], 1);
}

// single-pass scan: all 98 blocks resident; block b sums predecessors' aggregates
__global__ void k_scanlb() {
    __shared__ int sh[1024];
    __shared__ int spart[32];
    __shared__ int s_pref;
    int tid = threadIdx.x, b = blockIdx.x;
    int i = b * 1024 + tid;
    int v = (i < NODES) ? g_deg[i] : 0;
    sh[tid] = v;
    __syncthreads();
    for (int off = 1; off < 1024; off <<= 1) {
        int t = (tid >= off) ? sh[tid - off] : 0;
        __syncthreads();
        sh[tid] += t;
        __syncthreads();
    }
    if (tid == 1023) atomicExch(&g_aggpub[b], sh[1023]);   // publish aggregate

    int myv = 0;
    if (tid < b) {                                          // b <= 97 < 1024
        int t;
        do { t = atomicAdd(&g_aggpub[tid], 0); } while (t < 0);
        myv = t;
    }
#pragma unroll
    for (int off = 16; off; off >>= 1) myv += __shfl_xor_sync(0xffffffffu, myv, off);
    if ((tid & 31) == 0) spart[tid >> 5] = myv;
    __syncthreads();
    if (tid == 0) {
        int s = 0;
#pragma unroll
        for (int wdx = 0; wdx < 32; wdx++) s += spart[wdx];
        s_pref = s;
    }
    __syncthreads();
    if (i < NODES) {
        g_ptr[i] = s_pref + sh[tid] - v;                    // exclusive prefix
        g_inv[i] = (v > 0) ? (1.0f / (float)v) : 0.0f;
    }
    if (i == 0) g_ptr[NODES] = EDGES;
}

__global__ void k_fill(const int* __restrict__ src, const int* __restrict__ dst) {
    int e = blockIdx.x * blockDim.x + threadIdx.x;
    if (e < EDGES) {
        int d = dst[e];
        int pos = g_ptr[d] + atomicAdd(&g_fill[d], 1);
        g_csr[pos] = src[e];
    }
}

// ================= fused SAGE layer =================
// 256 threads, 8 warps x 8 nodes = 64 nodes/block.
// DIN=32: fp32 gather of x (128B rows). DIN=64: fp16 gather (128B rows).
// GEMM via FFMA2 with accumulator pair (sum a*Wn[f], sum h*Wr[f]).
template <int DIN, bool RELU, bool PRED>
__global__ void __launch_bounds__(256) k_sage(const float* __restrict__ hin,
                                              const __half2* __restrict__ hhin,
                                              const float* __restrict__ Wn,
                                              const float* __restrict__ bn,
                                              const float* __restrict__ Wr,
                                              const float* __restrict__ Wp1,
                                              const float* __restrict__ bp1,
                                              const float* __restrict__ Wp2,
                                              const float* __restrict__ bp2,
                                              float* __restrict__ hout,
                                              __half2* __restrict__ hhout,
                                              float* __restrict__ pred_out) {
    extern __shared__ ull dyn[];
    ull* sW0 = dyn;                  // [DIN*32] (Wn[i][2l],   Wr[i][2l])
    ull* sW1 = dyn + DIN * 32;       // [DIN*32] (Wn[i][2l+1], Wr[i][2l+1])
    ull* sAH = dyn + DIN * 64;       // [64*DIN] (agg, own) per [node][i]
    __shared__ float sV[64];

    int tid = threadIdx.x, w = tid >> 5, lane = tid & 31;
    int sb = w * 8;
    int n0 = blockIdx.x * 64;

    // ---- weights ----
    for (int idx = tid; idx < DIN * 32; idx += 256) {
        int i = idx >> 5, l = idx & 31;
        sW0[idx] = pack2(Wn[i * 64 + 2 * l],     Wr[i * 64 + 2 * l]);
        sW1[idx] = pack2(Wn[i * 64 + 2 * l + 1], Wr[i * 64 + 2 * l + 1]);
    }

    // ---- Phase A: aggregate (MLP-8 batched gather) ----
#pragma unroll 1
    for (int s = 0; s < 8; s++) {
        int sl = sb + s;
        int ng = n0 + sl;
        if (ng >= NODES) break;
        int beg = g_ptr[ng], end = g_ptr[ng + 1];
        float iv = g_inv[ng];
        if (DIN == 64) {
            float sx = 0.f, sy = 0.f;
            int k = beg;
            for (; k + 7 < end; k += 8) {
                int id[8];
#pragma unroll
                for (int j = 0; j < 8; j++) id[j] = g_csr[k + j];
                __half2 vv[8];
#pragma unroll
                for (int j = 0; j < 8; j++) vv[j] = hhin[id[j] * 32 + lane];
#pragma unroll
                for (int j = 0; j < 8; j++) {
                    float2 f = __half22float2(vv[j]);
                    sx += f.x; sy += f.y;
                }
            }
            for (; k < end; k++) {
                float2 f = __half22float2(hhin[g_csr[k] * 32 + lane]);
                sx += f.x; sy += f.y;
            }
            float2 own = ((const float2*)hin)[ng * 32 + lane];
            sAH[sl * 64 + 2 * lane]     = pack2(sx * iv, own.x);
            sAH[sl * 64 + 2 * lane + 1] = pack2(sy * iv, own.y);
        } else {   // DIN == 32, fp32 gather (rows are 128B already)
            float sm = 0.f;
            int k = beg;
            for (; k + 7 < end; k += 8) {
                int id[8];
#pragma unroll
                for (int j = 0; j < 8; j++) id[j] = g_csr[k + j];
                float vv[8];
#pragma unroll
                for (int j = 0; j < 8; j++) vv[j] = hin[id[j] * 32 + lane];
#pragma unroll
                for (int j = 0; j < 8; j++) sm += vv[j];
            }
            for (; k < end; k++) sm += hin[g_csr[k] * 32 + lane];
            float own = hin[ng * 32 + lane];
            sAH[sl * 32 + lane] = pack2(sm * iv, own);
        }
    }
    __syncthreads();

    // ---- Phase B: GEMM, lane owns output features (2*lane, 2*lane+1) ----
    ull acc0[8], acc1[8];
#pragma unroll
    for (int s = 0; s < 8; s++) { acc0[s] = 0ull; acc1[s] = 0ull; }

#pragma unroll 4
    for (int i = 0; i < DIN; i++) {
        ull w0 = sW0[i * 32 + lane];
        ull w1 = sW1[i * 32 + lane];
#pragma unroll
        for (int s = 0; s < 8; s++) {
            ull ah = sAH[(sb + s) * DIN + i];   // broadcast LDS.64
            acc0[s] = fma2(ah, w0, acc0[s]);
            acc1[s] = fma2(ah, w1, acc1[s]);
        }
    }

    float2 b2 = ((const float2*)bn)[lane];
    float rx[8], ry[8];
#pragma unroll
    for (int s = 0; s < 8; s++) {
        float2 v0 = unpack2(acc0[s]);
        float2 v1 = unpack2(acc1[s]);
        rx[s] = v0.x + v0.y + b2.x;
        ry[s] = v1.x + v1.y + b2.y;
        if (RELU) { rx[s] = fmaxf(rx[s], 0.f); ry[s] = fmaxf(ry[s], 0.f); }
    }

    if (!PRED) {
#pragma unroll
        for (int s = 0; s < 8; s++) {
            int ng = n0 + sb + s;
            if (ng < NODES) {
                ((float2*)hout)[ng * 32 + lane] = make_float2(rx[s], ry[s]);
                hhout[ng * 32 + lane] = __floats2half2_rn(rx[s], ry[s]);
            }
        }
        return;
    }

    // ---- PRED: sigmoid(relu(h@Wp1+bp1)@Wp2 + bp2) ----
    __syncthreads();                       // all warps done with sW/sAH
    float*  sH  = (float*)sAH;             // [64][64]  (16KB of 32KB)
    float2* sWp = (float2*)sW0;            // [64][32]  (16KB of 32KB)

#pragma unroll
    for (int s = 0; s < 8; s++) {
        sH[(sb + s) * 64 + 2 * lane]     = rx[s];
        sH[(sb + s) * 64 + 2 * lane + 1] = ry[s];
    }
    const float2* Wp12 = (const float2*)Wp1;
    for (int idx = tid; idx < 64 * 32; idx += 256) sWp[idx] = Wp12[idx];
    if (tid < 64) sV[tid] = Wp2[tid];
    __syncthreads();

    float2 bb = ((const float2*)bp1)[lane];
    float  vb = bp2[0];
#pragma unroll 1
    for (int s = 0; s < 8; s++) {
        float ax = bb.x, ay = bb.y;
#pragma unroll 8
        for (int i = 0; i < 64; i++) {
            float hh = sH[(sb + s) * 64 + i];
            float2 wv = sWp[i * 32 + lane];
            ax += hh * wv.x;
            ay += hh * wv.y;
        }
        ax = fmaxf(ax, 0.f);
        ay = fmaxf(ay, 0.f);
        float z = ax * sV[2 * lane] + ay * sV[2 * lane + 1];
#pragma unroll
        for (int off = 16; off; off >>= 1) z += __shfl_xor_sync(0xffffffffu, z, off);
        int ng = n0 + sb + s;
        if (lane == 0 && ng < NODES) pred_out[ng] = 1.f / (1.f + expf(-(z + vb)));
    }
}

// ---------------- launch ----------------
extern "C" void kernel_launch(void* const* d_in, const int* in_sizes, int n_in,
                              void* d_out, int out_size) {
    const float* x   = (const float*)d_in[0];
    const int*   ei  = (const int*)d_in[1];
    const int*   src = ei;
    const int*   dst = ei + EDGES;
    const float* Wn0 = (const float*)d_in[2];
    const float* bn0 = (const float*)d_in[3];
    const float* Wr0 = (const float*)d_in[4];
    const float* Wn1 = (const float*)d_in[5];
    const float* bn1 = (const float*)d_in[6];
    const float* Wr1 = (const float*)d_in[7];
    const float* Wn2 = (const float*)d_in[8];
    const float* bn2 = (const float*)d_in[9];
    const float* Wr2 = (const float*)d_in[10];
    const float* Wp1 = (const float*)d_in[11];
    const float* bp1 = (const float*)d_in[12];
    const float* Wp2 = (const float*)d_in[13];
    const float* bp2 = (const float*)d_in[14];
    float* out = (float*)d_out;

    float *pH0, *pH1;
    __half2 *pHH0, *pHH1;
    int *pDeg, *pFill, *pAggpub;
    cudaGetSymbolAddress((void**)&pH0, g_h0);
    cudaGetSymbolAddress((void**)&pH1, g_h1);
    cudaGetSymbolAddress((void**)&pHH0, g_hh0);
    cudaGetSymbolAddress((void**)&pHH1, g_hh1);
    cudaGetSymbolAddress((void**)&pDeg, g_deg);
    cudaGetSymbolAddress((void**)&pFill, g_fill);
    cudaGetSymbolAddress((void**)&pAggpub, g_aggpub);

    // raise dynamic smem limit for the 64KB variants (idempotent host calls)
    cudaFuncSetAttribute(k_sage<64, true,  false>,
                         cudaFuncAttributeMaxDynamicSharedMemorySize, 65536);
    cudaFuncSetAttribute(k_sage<64, false, true>,
                         cudaFuncAttributeMaxDynamicSharedMemorySize, 65536);

    // zeroing via memset nodes (not kernel launches)
    cudaMemsetAsync(pDeg, 0, NODES * sizeof(int));
    cudaMemsetAsync(pFill, 0, NODES * sizeof(int));
    cudaMemsetAsync(pAggpub, 0xFF, SCAN_NB * sizeof(int));   // -1 sentinel

    // CSR build: 3 kernels
    k_hist<<<(EDGES + 255) / 256, 256>>>(dst);
    k_scanlb<<<SCAN_NB, 1024>>>();
    k_fill<<<(EDGES + 255) / 256, 256>>>(src, dst);

    const int GRID = (NODES + 63) / 64;   // 1563
    // layer 0: 32 -> 64, relu (fp32 gather of x)
    k_sage<32, true,  false><<<GRID, 256, 32768>>>(x, nullptr, Wn0, bn0, Wr0,
            nullptr, nullptr, nullptr, nullptr, pH0, pHH0, nullptr);
    // layer 1: 64 -> 64, relu (fp16 gather)
    k_sage<64, true,  false><<<GRID, 256, 65536>>>(pH0, pHH0, Wn1, bn1, Wr1,
            nullptr, nullptr, nullptr, nullptr, pH1, pHH1, nullptr);
    // layer 2: 64 -> 64, no relu, predictor fused
    k_sage<64, false, true ><<<GRID, 256, 65536>>>(pH1, pHH1, Wn2, bn2, Wr2,
            Wp1, bp1, Wp2, bp2, nullptr, nullptr, out);

    (void)in_sizes; (void)n_in; (void)out_size;
}